// round 2
// baseline (speedup 1.0000x reference)
#include <cuda_runtime.h>

#define N_NODES 100000
#define N_EDGES 1600000
#define EN_TOT  (N_EDGES + N_NODES)   // edges + self loops
#define F_IN    512
#define H1      8
#define C1      8
#define D1      64                    // H1*C1
#define C2      40

// ---------------- scratch (static device allocations; allowed) ----------------
__device__ float g_h1 [N_NODES * D1];   // layer1 linear output  [N,64]
__device__ float g_as1[N_NODES * H1];   // per-node src attention [N,8]
__device__ float g_ad1[N_NODES * H1];
__device__ float g_den1[N_NODES * H1];  // softmax denominators
__device__ float g_out1[N_NODES * D1];  // layer1 aggregated output
__device__ float g_h2 [N_NODES * C2];   // layer2 linear output  [N,40]
__device__ float g_as2[N_NODES];
__device__ float g_ad2[N_NODES];
__device__ float g_den2[N_NODES];

__device__ __forceinline__ void red_add_v4(float* addr, float a, float b, float c, float d) {
    asm volatile("red.global.add.v4.f32 [%0], {%1,%2,%3,%4};"
                 :: "l"(addr), "f"(a), "f"(b), "f"(c), "f"(d) : "memory");
}
__device__ __forceinline__ float lrelu(float e) { return e > 0.f ? e : 0.2f * e; }

// =============================================================================
// GEMM1: g_h1[N,64] = x[N,512] @ W1[512,64]   (fp32 SIMT, BM=128 BN=64 BK=32)
// =============================================================================
#define BM 128
#define BN 64
#define BK 32
__global__ __launch_bounds__(256) void k_gemm1(const float* __restrict__ X,
                                               const float* __restrict__ W) {
    __shared__ float As[BK][BM + 1];   // +1 pad: conflict-free scattered stores
    __shared__ float Bs[BK][BN];

    const int tid = threadIdx.x;
    const int tx = tid & 15;           // 16 col groups (TN=4)
    const int ty = tid >> 4;           // 16 row groups (TM=8)
    const int row0 = blockIdx.x * BM;

    float acc[8][4] = {};

    for (int k0 = 0; k0 < F_IN; k0 += BK) {
        // A tile: 128x32 floats, 1024 float4, 4 per thread
#pragma unroll
        for (int i = 0; i < 4; i++) {
            int fid = tid + i * 256;        // 0..1023
            int r = fid >> 3;               // 8 float4 per row
            int c4 = fid & 7;
            int gr = row0 + r;
            if (gr >= N_NODES) gr = N_NODES - 1;
            float4 v = *(const float4*)&X[(size_t)gr * F_IN + k0 + c4 * 4];
            As[c4 * 4 + 0][r] = v.x;
            As[c4 * 4 + 1][r] = v.y;
            As[c4 * 4 + 2][r] = v.z;
            As[c4 * 4 + 3][r] = v.w;
        }
        // B tile: 32x64 floats, 512 float4, 2 per thread
#pragma unroll
        for (int i = 0; i < 2; i++) {
            int fid = tid + i * 256;        // 0..511
            int r = fid >> 4;               // 16 float4 per row
            int c4 = fid & 15;
            *(float4*)&Bs[r][c4 * 4] = *(const float4*)&W[(k0 + r) * BN + c4 * 4];
        }
        __syncthreads();
#pragma unroll
        for (int kk = 0; kk < BK; kk++) {
            float a[8], b[4];
#pragma unroll
            for (int i = 0; i < 8; i++) a[i] = As[kk][ty * 8 + i];
            float4 bv = *(const float4*)&Bs[kk][tx * 4];
            b[0] = bv.x; b[1] = bv.y; b[2] = bv.z; b[3] = bv.w;
#pragma unroll
            for (int i = 0; i < 8; i++)
#pragma unroll
                for (int j = 0; j < 4; j++) acc[i][j] += a[i] * b[j];
        }
        __syncthreads();
    }
#pragma unroll
    for (int i = 0; i < 8; i++) {
        int gr = row0 + ty * 8 + i;
        if (gr < N_NODES)
            *(float4*)&g_h1[(size_t)gr * D1 + tx * 4] =
                make_float4(acc[i][0], acc[i][1], acc[i][2], acc[i][3]);
    }
}

// =============================================================================
// att1: per (node,head) attention scalars
// =============================================================================
__global__ void k_att1(const float* __restrict__ att_src, const float* __restrict__ att_dst) {
    int idx = blockIdx.x * blockDim.x + threadIdx.x;
    if (idx >= N_NODES * H1) return;
    int h = idx & 7, n = idx >> 3;
    const float4* hp = (const float4*)&g_h1[(size_t)n * D1 + h * C1];
    float4 h0 = hp[0], h1v = hp[1];
    const float4* sp = (const float4*)&att_src[h * C1];
    const float4* dp = (const float4*)&att_dst[h * C1];
    float4 s0 = sp[0], s1 = sp[1], d0 = dp[0], d1 = dp[1];
    g_as1[idx] = h0.x * s0.x + h0.y * s0.y + h0.z * s0.z + h0.w * s0.w
               + h1v.x * s1.x + h1v.y * s1.y + h1v.z * s1.z + h1v.w * s1.w;
    g_ad1[idx] = h0.x * d0.x + h0.y * d0.y + h0.z * d0.z + h0.w * d0.w
               + h1v.x * d1.x + h1v.y * d1.y + h1v.z * d1.z + h1v.w * d1.w;
}

// edge_index is int32 on device (JAX x64 disabled downgrades int64 -> int32).
__device__ __forceinline__ void edge_sd(const int* __restrict__ ei, int i, int& s, int& d) {
    if (i < N_EDGES) { s = ei[i]; d = ei[N_EDGES + i]; }
    else             { s = d = i - N_EDGES; }
}

// =============================================================================
// edge pass 1a: softmax denominators (no max-shift: self-loops guarantee denom>0,
// logits bounded -> exp() safe in fp32)
// =============================================================================
__global__ void k_edge_den1(const int* __restrict__ ei) {
    int i = blockIdx.x * blockDim.x + threadIdx.x;
    if (i >= EN_TOT) return;
    int s, d; edge_sd(ei, i, s, d);
    const float4* ap = (const float4*)&g_as1[s * H1];
    const float4* bp = (const float4*)&g_ad1[d * H1];
    float4 a0 = ap[0], a1 = ap[1], b0 = bp[0], b1 = bp[1];
    float w0 = __expf(lrelu(a0.x + b0.x));
    float w1 = __expf(lrelu(a0.y + b0.y));
    float w2 = __expf(lrelu(a0.z + b0.z));
    float w3 = __expf(lrelu(a0.w + b0.w));
    float w4 = __expf(lrelu(a1.x + b1.x));
    float w5 = __expf(lrelu(a1.y + b1.y));
    float w6 = __expf(lrelu(a1.z + b1.z));
    float w7 = __expf(lrelu(a1.w + b1.w));
    red_add_v4(&g_den1[d * H1],     w0, w1, w2, w3);
    red_add_v4(&g_den1[d * H1 + 4], w4, w5, w6, w7);
}

// =============================================================================
// edge pass 1b: weighted aggregation into g_out1
// =============================================================================
__global__ void k_edge_agg1(const int* __restrict__ ei) {
    int i = blockIdx.x * blockDim.x + threadIdx.x;
    if (i >= EN_TOT) return;
    int s, d; edge_sd(ei, i, s, d);
    const float4* ap = (const float4*)&g_as1[s * H1];
    const float4* bp = (const float4*)&g_ad1[d * H1];
    const float4* qp = (const float4*)&g_den1[d * H1];
    float4 a0 = ap[0], a1 = ap[1], b0 = bp[0], b1 = bp[1], q0 = qp[0], q1 = qp[1];
    float al[8];
    al[0] = __expf(lrelu(a0.x + b0.x)) / (q0.x + 1e-16f);
    al[1] = __expf(lrelu(a0.y + b0.y)) / (q0.y + 1e-16f);
    al[2] = __expf(lrelu(a0.z + b0.z)) / (q0.z + 1e-16f);
    al[3] = __expf(lrelu(a0.w + b0.w)) / (q0.w + 1e-16f);
    al[4] = __expf(lrelu(a1.x + b1.x)) / (q1.x + 1e-16f);
    al[5] = __expf(lrelu(a1.y + b1.y)) / (q1.y + 1e-16f);
    al[6] = __expf(lrelu(a1.z + b1.z)) / (q1.z + 1e-16f);
    al[7] = __expf(lrelu(a1.w + b1.w)) / (q1.w + 1e-16f);
    const float4* hp = (const float4*)&g_h1[(size_t)s * D1];
    float* op = &g_out1[(size_t)d * D1];
#pragma unroll
    for (int c4 = 0; c4 < 16; c4++) {
        float4 h = hp[c4];
        float a = al[c4 >> 1];
        red_add_v4(op + c4 * 4, h.x * a, h.y * a, h.z * a, h.w * a);
    }
}

// =============================================================================
// layer2 prep: per node: v = relu(out1 + b1); h2 = v @ W2; att scalars.
// warp per node, W2 staged in smem.
// =============================================================================
__global__ __launch_bounds__(256) void k_l2prep(const float* __restrict__ b1,
                                                const float* __restrict__ W2,
                                                const float* __restrict__ att_src2,
                                                const float* __restrict__ att_dst2) {
    __shared__ float W2s[D1 * C2];
    __shared__ float b1s[D1];
    __shared__ float s2s[C2];
    __shared__ float d2s[C2];
    __shared__ float vbuf[8][D1];

    for (int i = threadIdx.x; i < D1 * C2; i += 256) W2s[i] = W2[i];
    if (threadIdx.x < D1) b1s[threadIdx.x] = b1[threadIdx.x];
    if (threadIdx.x < C2) s2s[threadIdx.x] = att_src2[threadIdx.x];
    if (threadIdx.x >= 64 && threadIdx.x < 64 + C2) d2s[threadIdx.x - 64] = att_dst2[threadIdx.x - 64];
    __syncthreads();

    const int w = threadIdx.x >> 5;
    const int lane = threadIdx.x & 31;
    const int n = blockIdx.x * 8 + w;
    if (n >= N_NODES) return;

    const float* in = &g_out1[(size_t)n * D1];
    float v0 = in[lane]      + b1s[lane];        v0 = v0 > 0.f ? v0 : 0.f;
    float v1 = in[lane + 32] + b1s[lane + 32];   v1 = v1 > 0.f ? v1 : 0.f;
    vbuf[w][lane] = v0;
    vbuf[w][lane + 32] = v1;
    __syncwarp();

    float ps = 0.f, pd = 0.f;
    for (int c = lane; c < C2; c += 32) {
        float acc = 0.f;
#pragma unroll
        for (int k = 0; k < D1; k++) acc += vbuf[w][k] * W2s[k * C2 + c];
        g_h2[(size_t)n * C2 + c] = acc;
        ps += acc * s2s[c];
        pd += acc * d2s[c];
    }
#pragma unroll
    for (int o = 16; o; o >>= 1) {
        ps += __shfl_xor_sync(0xffffffffu, ps, o);
        pd += __shfl_xor_sync(0xffffffffu, pd, o);
    }
    if (lane == 0) { g_as2[n] = ps; g_ad2[n] = pd; }
}

// =============================================================================
// edge pass 2a / 2b (single head, C=40)
// =============================================================================
__global__ void k_edge_den2(const int* __restrict__ ei) {
    int i = blockIdx.x * blockDim.x + threadIdx.x;
    if (i >= EN_TOT) return;
    int s, d; edge_sd(ei, i, s, d);
    float wv = __expf(lrelu(g_as2[s] + g_ad2[d]));
    atomicAdd(&g_den2[d], wv);
}

__global__ void k_edge_agg2(const int* __restrict__ ei, float* __restrict__ out) {
    int i = blockIdx.x * blockDim.x + threadIdx.x;
    if (i >= EN_TOT) return;
    int s, d; edge_sd(ei, i, s, d);
    float al = __expf(lrelu(g_as2[s] + g_ad2[d])) / (g_den2[d] + 1e-16f);
    const float4* hp = (const float4*)&g_h2[(size_t)s * C2];
    float* op = &out[(size_t)d * C2];
#pragma unroll
    for (int c4 = 0; c4 < 10; c4++) {
        float4 h = hp[c4];
        red_add_v4(op + c4 * 4, h.x * al, h.y * al, h.z * al, h.w * al);
    }
}

// =============================================================================
// finalize: out = log_softmax(out + b2) per node over 40 classes (warp/node)
// =============================================================================
__global__ __launch_bounds__(256) void k_final(float* __restrict__ out,
                                               const float* __restrict__ b2) {
    const int w = threadIdx.x >> 5;
    const int lane = threadIdx.x & 31;
    const int n = blockIdx.x * 8 + w;
    if (n >= N_NODES) return;
    float* row = &out[(size_t)n * C2];
    float x0 = row[lane] + b2[lane];
    float x1 = (lane < 8) ? row[32 + lane] + b2[32 + lane] : -1e30f;
    float m = fmaxf(x0, x1);
#pragma unroll
    for (int o = 16; o; o >>= 1) m = fmaxf(m, __shfl_xor_sync(0xffffffffu, m, o));
    float s = expf(x0 - m) + ((lane < 8) ? expf(x1 - m) : 0.f);
#pragma unroll
    for (int o = 16; o; o >>= 1) s += __shfl_xor_sync(0xffffffffu, s, o);
    float l = m + logf(s);
    row[lane] = x0 - l;
    if (lane < 8) row[32 + lane] = x1 - l;
}

// =============================================================================
extern "C" void kernel_launch(void* const* d_in, const int* in_sizes, int n_in,
                              void* d_out, int out_size) {
    const float* x        = (const float*)d_in[0];
    const int*   ei       = (const int*)d_in[1];
    const float* W1       = (const float*)d_in[2];
    const float* att_src1 = (const float*)d_in[3];
    const float* att_dst1 = (const float*)d_in[4];
    const float* b1       = (const float*)d_in[5];
    const float* W2       = (const float*)d_in[6];
    const float* att_src2 = (const float*)d_in[7];
    const float* att_dst2 = (const float*)d_in[8];
    const float* b2       = (const float*)d_in[9];
    float*       out      = (float*)d_out;
    (void)in_sizes; (void)n_in;

    void *p_den1, *p_out1, *p_den2;
    cudaGetSymbolAddress(&p_den1, g_den1);
    cudaGetSymbolAddress(&p_out1, g_out1);
    cudaGetSymbolAddress(&p_den2, g_den2);

    cudaMemsetAsync(p_den1, 0, (size_t)N_NODES * H1 * sizeof(float));
    cudaMemsetAsync(p_out1, 0, (size_t)N_NODES * D1 * sizeof(float));
    cudaMemsetAsync(p_den2, 0, (size_t)N_NODES * sizeof(float));
    cudaMemsetAsync(out,    0, (size_t)out_size * sizeof(float));

    const int TB = 256;
    k_gemm1<<<(N_NODES + BM - 1) / BM, TB>>>(x, W1);
    k_att1<<<(N_NODES * H1 + TB - 1) / TB, TB>>>(att_src1, att_dst1);
    k_edge_den1<<<(EN_TOT + TB - 1) / TB, TB>>>(ei);
    k_edge_agg1<<<(EN_TOT + TB - 1) / TB, TB>>>(ei);
    k_l2prep<<<(N_NODES + 7) / 8, TB>>>(b1, W2, att_src2, att_dst2);
    k_edge_den2<<<(EN_TOT + TB - 1) / TB, TB>>>(ei);
    k_edge_agg2<<<(EN_TOT + TB - 1) / TB, TB>>>(ei, out);
    k_final<<<(N_NODES + 7) / 8, TB>>>(out, b2);
}

// round 3
// speedup vs baseline: 1.2584x; 1.2584x over previous
#include <cuda_runtime.h>

#define N_NODES 100000
#define N_EDGES 1600000
#define EN_TOT  (N_EDGES + N_NODES)   // edges + self loops
#define F_IN    512
#define H1      8
#define C1      8
#define D1      64                    // H1*C1
#define C2      40

// ---------------- scratch (static device allocations; allowed) ----------------
__device__ float g_h1 [N_NODES * D1];   // layer1 linear output  [N,64]
__device__ float g_as1[N_NODES * H1];   // per-node src attention [N,8]
__device__ float g_ad1[N_NODES * H1];
__device__ float g_den1[N_NODES * H1];  // softmax denominators
__device__ float g_out1[N_NODES * D1];  // layer1 aggregated output
__device__ float g_h2 [N_NODES * C2];   // layer2 linear output  [N,40]
__device__ float g_as2[N_NODES];
__device__ float g_ad2[N_NODES];
__device__ float g_den2[N_NODES];

__device__ __forceinline__ void red_add_v4(float* addr, float a, float b, float c, float d) {
    asm volatile("red.global.add.v4.f32 [%0], {%1,%2,%3,%4};"
                 :: "l"(addr), "f"(a), "f"(b), "f"(c), "f"(d) : "memory");
}
__device__ __forceinline__ void red_add_f(float* addr, float a) {
    asm volatile("red.global.add.f32 [%0], %1;" :: "l"(addr), "f"(a) : "memory");
}
__device__ __forceinline__ float lrelu(float e) { return e > 0.f ? e : 0.2f * e; }

// edge_index is int32 on device (JAX x64 disabled downgrades int64 -> int32).
__device__ __forceinline__ void edge_sd(const int* __restrict__ ei, int i, int& s, int& d) {
    if (i < N_EDGES) { s = __ldg(&ei[i]); d = __ldg(&ei[N_EDGES + i]); }
    else             { s = d = i - N_EDGES; }
}

// =============================================================================
// GEMM1: g_h1[N,64] = x[N,512] @ W1[512,64]   (fp32 SIMT, BM=128 BN=64 BK=32)
// =============================================================================
#define BM 128
#define BN 64
#define BK 32
__global__ __launch_bounds__(256) void k_gemm1(const float* __restrict__ X,
                                               const float* __restrict__ W) {
    __shared__ float As[BK][BM + 1];   // +1 pad: conflict-free scattered stores
    __shared__ float Bs[BK][BN];

    const int tid = threadIdx.x;
    const int tx = tid & 15;           // 16 col groups (TN=4)
    const int ty = tid >> 4;           // 16 row groups (TM=8)
    const int row0 = blockIdx.x * BM;

    float acc[8][4] = {};

    for (int k0 = 0; k0 < F_IN; k0 += BK) {
        // A tile: 128x32 floats, 1024 float4, 4 per thread
#pragma unroll
        for (int i = 0; i < 4; i++) {
            int fid = tid + i * 256;        // 0..1023
            int r = fid >> 3;               // 8 float4 per row
            int c4 = fid & 7;
            int gr = row0 + r;
            if (gr >= N_NODES) gr = N_NODES - 1;
            float4 v = *(const float4*)&X[(size_t)gr * F_IN + k0 + c4 * 4];
            As[c4 * 4 + 0][r] = v.x;
            As[c4 * 4 + 1][r] = v.y;
            As[c4 * 4 + 2][r] = v.z;
            As[c4 * 4 + 3][r] = v.w;
        }
        // B tile: 32x64 floats, 512 float4, 2 per thread
#pragma unroll
        for (int i = 0; i < 2; i++) {
            int fid = tid + i * 256;        // 0..511
            int r = fid >> 4;               // 16 float4 per row
            int c4 = fid & 15;
            *(float4*)&Bs[r][c4 * 4] = *(const float4*)&W[(k0 + r) * BN + c4 * 4];
        }
        __syncthreads();
#pragma unroll
        for (int kk = 0; kk < BK; kk++) {
            float a[8], b[4];
#pragma unroll
            for (int i = 0; i < 8; i++) a[i] = As[kk][ty * 8 + i];
            float4 bv = *(const float4*)&Bs[kk][tx * 4];
            b[0] = bv.x; b[1] = bv.y; b[2] = bv.z; b[3] = bv.w;
#pragma unroll
            for (int i = 0; i < 8; i++)
#pragma unroll
                for (int j = 0; j < 4; j++) acc[i][j] += a[i] * b[j];
        }
        __syncthreads();
    }
#pragma unroll
    for (int i = 0; i < 8; i++) {
        int gr = row0 + ty * 8 + i;
        if (gr < N_NODES)
            *(float4*)&g_h1[(size_t)gr * D1 + tx * 4] =
                make_float4(acc[i][0], acc[i][1], acc[i][2], acc[i][3]);
    }
}

// =============================================================================
// att1: per (node,head) attention scalars
// =============================================================================
__global__ void k_att1(const float* __restrict__ att_src, const float* __restrict__ att_dst) {
    int idx = blockIdx.x * blockDim.x + threadIdx.x;
    if (idx >= N_NODES * H1) return;
    int h = idx & 7, n = idx >> 3;
    const float4* hp = (const float4*)&g_h1[(size_t)n * D1 + h * C1];
    float4 h0 = hp[0], h1v = hp[1];
    const float4* sp = (const float4*)&att_src[h * C1];
    const float4* dp = (const float4*)&att_dst[h * C1];
    float4 s0 = sp[0], s1 = sp[1], d0 = dp[0], d1 = dp[1];
    g_as1[idx] = h0.x * s0.x + h0.y * s0.y + h0.z * s0.z + h0.w * s0.w
               + h1v.x * s1.x + h1v.y * s1.y + h1v.z * s1.z + h1v.w * s1.w;
    g_ad1[idx] = h0.x * d0.x + h0.y * d0.y + h0.z * d0.z + h0.w * d0.w
               + h1v.x * d1.x + h1v.y * d1.y + h1v.z * d1.z + h1v.w * d1.w;
}

// =============================================================================
// edge pass 1a: softmax denominators.  8 lanes per edge, lane == head.
// All gathers/reds are 32B-coalesced across the 8 lanes of an edge.
// (No max-shift: self-loops guarantee denom>0, logits bounded -> fp32 exp safe.)
// =============================================================================
__global__ void k_edge_den1(const int* __restrict__ ei) {
    int t = blockIdx.x * blockDim.x + threadIdx.x;
    int e = t >> 3, l = t & 7;
    if (e >= EN_TOT) return;
    int s, d; edge_sd(ei, e, s, d);
    float w = __expf(lrelu(g_as1[s * H1 + l] + g_ad1[d * H1 + l]));
    red_add_f(&g_den1[d * H1 + l], w);
}

// =============================================================================
// edge pass 1b: weighted aggregation. 8 lanes per edge, lane l owns head l
// = feature slice [l*8, l*8+8).  h1-row load: 256B contiguous per edge;
// red.v4 targets: 256B contiguous per edge.
// =============================================================================
__global__ void k_edge_agg1(const int* __restrict__ ei) {
    int t = blockIdx.x * blockDim.x + threadIdx.x;
    int e = t >> 3, l = t & 7;
    if (e >= EN_TOT) return;
    int s, d; edge_sd(ei, e, s, d);
    float as = g_as1[s * H1 + l];
    float ad = g_ad1[d * H1 + l];
    float dn = g_den1[d * H1 + l];
    float al = __expf(lrelu(as + ad)) / (dn + 1e-16f);
    const float4* hp = (const float4*)&g_h1[(size_t)s * D1 + l * C1];
    float4 h0 = hp[0], h1v = hp[1];
    float* op = &g_out1[(size_t)d * D1 + l * C1];
    red_add_v4(op,     h0.x * al, h0.y * al, h0.z * al, h0.w * al);
    red_add_v4(op + 4, h1v.x * al, h1v.y * al, h1v.z * al, h1v.w * al);
}

// =============================================================================
// layer2 prep: per node: v = relu(out1 + b1); h2 = v @ W2; att scalars.
// warp per node, W2 staged in smem.
// =============================================================================
__global__ __launch_bounds__(256) void k_l2prep(const float* __restrict__ b1,
                                                const float* __restrict__ W2,
                                                const float* __restrict__ att_src2,
                                                const float* __restrict__ att_dst2) {
    __shared__ float W2s[D1 * C2];
    __shared__ float b1s[D1];
    __shared__ float s2s[C2];
    __shared__ float d2s[C2];
    __shared__ float vbuf[8][D1];

    for (int i = threadIdx.x; i < D1 * C2; i += 256) W2s[i] = W2[i];
    if (threadIdx.x < D1) b1s[threadIdx.x] = b1[threadIdx.x];
    if (threadIdx.x < C2) s2s[threadIdx.x] = att_src2[threadIdx.x];
    if (threadIdx.x >= 64 && threadIdx.x < 64 + C2) d2s[threadIdx.x - 64] = att_dst2[threadIdx.x - 64];
    __syncthreads();

    const int w = threadIdx.x >> 5;
    const int lane = threadIdx.x & 31;
    const int n = blockIdx.x * 8 + w;
    if (n >= N_NODES) return;

    const float* in = &g_out1[(size_t)n * D1];
    float v0 = in[lane]      + b1s[lane];        v0 = v0 > 0.f ? v0 : 0.f;
    float v1 = in[lane + 32] + b1s[lane + 32];   v1 = v1 > 0.f ? v1 : 0.f;
    vbuf[w][lane] = v0;
    vbuf[w][lane + 32] = v1;
    __syncwarp();

    float ps = 0.f, pd = 0.f;
    for (int c = lane; c < C2; c += 32) {
        float acc = 0.f;
#pragma unroll
        for (int k = 0; k < D1; k++) acc += vbuf[w][k] * W2s[k * C2 + c];
        g_h2[(size_t)n * C2 + c] = acc;
        ps += acc * s2s[c];
        pd += acc * d2s[c];
    }
#pragma unroll
    for (int o = 16; o; o >>= 1) {
        ps += __shfl_xor_sync(0xffffffffu, ps, o);
        pd += __shfl_xor_sync(0xffffffffu, pd, o);
    }
    if (lane == 0) { g_as2[n] = ps; g_ad2[n] = pd; }
}

// =============================================================================
// edge pass 2a: denominators (single head) — 1 thread/edge scalar red
// =============================================================================
__global__ void k_edge_den2(const int* __restrict__ ei) {
    int i = blockIdx.x * blockDim.x + threadIdx.x;
    if (i >= EN_TOT) return;
    int s, d; edge_sd(ei, i, s, d);
    float wv = __expf(lrelu(g_as2[s] + g_ad2[d]));
    red_add_f(&g_den2[d], wv);
}

// =============================================================================
// edge pass 2b: aggregation, C=40 = 10 float4 chunks.  8 lanes per edge:
// lane l does chunk l; lanes 0,1 also do chunks 8,9.  Row stride 160B is
// 16B aligned so v4 reds are legal; loads/reds span contiguous 160B.
// =============================================================================
__global__ void k_edge_agg2(const int* __restrict__ ei, float* __restrict__ out) {
    int t = blockIdx.x * blockDim.x + threadIdx.x;
    int e = t >> 3, l = t & 7;
    if (e >= EN_TOT) return;
    int s, d; edge_sd(ei, e, s, d);
    float al = __expf(lrelu(g_as2[s] + g_ad2[d])) / (g_den2[d] + 1e-16f);
    const float4* hp = (const float4*)&g_h2[(size_t)s * C2];
    float* op = &out[(size_t)d * C2];
    float4 h = hp[l];
    red_add_v4(op + l * 4, h.x * al, h.y * al, h.z * al, h.w * al);
    if (l < 2) {
        float4 h2v = hp[8 + l];
        red_add_v4(op + (8 + l) * 4, h2v.x * al, h2v.y * al, h2v.z * al, h2v.w * al);
    }
}

// =============================================================================
// finalize: out = log_softmax(out + b2) per node over 40 classes (warp/node)
// =============================================================================
__global__ __launch_bounds__(256) void k_final(float* __restrict__ out,
                                               const float* __restrict__ b2) {
    const int w = threadIdx.x >> 5;
    const int lane = threadIdx.x & 31;
    const int n = blockIdx.x * 8 + w;
    if (n >= N_NODES) return;
    float* row = &out[(size_t)n * C2];
    float x0 = row[lane] + b2[lane];
    float x1 = (lane < 8) ? row[32 + lane] + b2[32 + lane] : -1e30f;
    float m = fmaxf(x0, x1);
#pragma unroll
    for (int o = 16; o; o >>= 1) m = fmaxf(m, __shfl_xor_sync(0xffffffffu, m, o));
    float s = expf(x0 - m) + ((lane < 8) ? expf(x1 - m) : 0.f);
#pragma unroll
    for (int o = 16; o; o >>= 1) s += __shfl_xor_sync(0xffffffffu, s, o);
    float l = m + logf(s);
    row[lane] = x0 - l;
    if (lane < 8) row[32 + lane] = x1 - l;
}

// =============================================================================
extern "C" void kernel_launch(void* const* d_in, const int* in_sizes, int n_in,
                              void* d_out, int out_size) {
    const float* x        = (const float*)d_in[0];
    const int*   ei       = (const int*)d_in[1];
    const float* W1       = (const float*)d_in[2];
    const float* att_src1 = (const float*)d_in[3];
    const float* att_dst1 = (const float*)d_in[4];
    const float* b1       = (const float*)d_in[5];
    const float* W2       = (const float*)d_in[6];
    const float* att_src2 = (const float*)d_in[7];
    const float* att_dst2 = (const float*)d_in[8];
    const float* b2       = (const float*)d_in[9];
    float*       out      = (float*)d_out;
    (void)in_sizes; (void)n_in;

    void *p_den1, *p_out1, *p_den2;
    cudaGetSymbolAddress(&p_den1, g_den1);
    cudaGetSymbolAddress(&p_out1, g_out1);
    cudaGetSymbolAddress(&p_den2, g_den2);

    cudaMemsetAsync(p_den1, 0, (size_t)N_NODES * H1 * sizeof(float));
    cudaMemsetAsync(p_out1, 0, (size_t)N_NODES * D1 * sizeof(float));
    cudaMemsetAsync(p_den2, 0, (size_t)N_NODES * sizeof(float));
    cudaMemsetAsync(out,    0, (size_t)out_size * sizeof(float));

    const int TB = 256;
    k_gemm1<<<(N_NODES + BM - 1) / BM, TB>>>(x, W1);
    k_att1<<<(N_NODES * H1 + TB - 1) / TB, TB>>>(att_src1, att_dst1);
    k_edge_den1<<<((EN_TOT * 8) + TB - 1) / TB, TB>>>(ei);
    k_edge_agg1<<<((EN_TOT * 8) + TB - 1) / TB, TB>>>(ei);
    k_l2prep<<<(N_NODES + 7) / 8, TB>>>(b1, W2, att_src2, att_dst2);
    k_edge_den2<<<(EN_TOT + TB - 1) / TB, TB>>>(ei);
    k_edge_agg2<<<((EN_TOT * 8) + TB - 1) / TB, TB>>>(ei, out);
    k_final<<<(N_NODES + 7) / 8, TB>>>(out, b2);
}

// round 6
// speedup vs baseline: 1.3728x; 1.0910x over previous
#include <cuda_runtime.h>

#define N_NODES 100000
#define N_EDGES 1600000
#define EN_TOT  (N_EDGES + N_NODES)   // edges + self loops
#define F_IN    512
#define H1      8
#define C1      8
#define D1      64                    // H1*C1
#define C2      40

// ---------------- scratch (static device allocations; allowed) ----------------
__device__ float g_h1 [N_NODES * D1];   // layer1 linear output  [N,64]
__device__ float g_as1[N_NODES * H1];   // per-node src attention [N,8]
__device__ float g_ad1[N_NODES * H1];
__device__ float g_den1[N_NODES * H1];  // softmax denominators (accumulated in agg pass)
__device__ float g_out1[N_NODES * D1];  // layer1 UNNORMALIZED aggregate
__device__ float g_h2 [N_NODES * C2];   // layer2 linear output  [N,40]
__device__ float g_as2[N_NODES];
__device__ float g_ad2[N_NODES];
__device__ float g_den2[N_NODES];

__device__ __forceinline__ void red_add_v4(float* addr, float a, float b, float c, float d) {
    asm volatile("red.global.add.v4.f32 [%0], {%1,%2,%3,%4};"
                 :: "l"(addr), "f"(a), "f"(b), "f"(c), "f"(d) : "memory");
}
__device__ __forceinline__ void red_add_f(float* addr, float a) {
    asm volatile("red.global.add.f32 [%0], %1;" :: "l"(addr), "f"(a) : "memory");
}
__device__ __forceinline__ float lrelu(float e) { return e > 0.f ? e : 0.2f * e; }

// edge_index is int32 on device.
__device__ __forceinline__ void edge_sd(const int* __restrict__ ei, int i, int& s, int& d) {
    if (i < N_EDGES) { s = __ldg(&ei[i]); d = __ldg(&ei[N_EDGES + i]); }
    else             { s = d = i - N_EDGES; }
}

// =============================================================================
// GEMM1: g_h1[N,64] = x[N,512] @ W1[512,64]   (fp32 SIMT, BM=128 BN=64 BK=32)
// =============================================================================
#define BM 128
#define BN 64
#define BK 32
__global__ __launch_bounds__(256) void k_gemm1(const float* __restrict__ X,
                                               const float* __restrict__ W) {
    __shared__ float As[BK][BM + 1];
    __shared__ float Bs[BK][BN];

    const int tid = threadIdx.x;
    const int tx = tid & 15;
    const int ty = tid >> 4;
    const int row0 = blockIdx.x * BM;

    float acc[8][4] = {};

    for (int k0 = 0; k0 < F_IN; k0 += BK) {
#pragma unroll
        for (int i = 0; i < 4; i++) {
            int fid = tid + i * 256;
            int r = fid >> 3;
            int c4 = fid & 7;
            int gr = row0 + r;
            if (gr >= N_NODES) gr = N_NODES - 1;
            float4 v = *(const float4*)&X[(size_t)gr * F_IN + k0 + c4 * 4];
            As[c4 * 4 + 0][r] = v.x;
            As[c4 * 4 + 1][r] = v.y;
            As[c4 * 4 + 2][r] = v.z;
            As[c4 * 4 + 3][r] = v.w;
        }
#pragma unroll
        for (int i = 0; i < 2; i++) {
            int fid = tid + i * 256;
            int r = fid >> 4;
            int c4 = fid & 15;
            *(float4*)&Bs[r][c4 * 4] = *(const float4*)&W[(k0 + r) * BN + c4 * 4];
        }
        __syncthreads();
#pragma unroll
        for (int kk = 0; kk < BK; kk++) {
            float a[8], b[4];
#pragma unroll
            for (int i = 0; i < 8; i++) a[i] = As[kk][ty * 8 + i];
            float4 bv = *(const float4*)&Bs[kk][tx * 4];
            b[0] = bv.x; b[1] = bv.y; b[2] = bv.z; b[3] = bv.w;
#pragma unroll
            for (int i = 0; i < 8; i++)
#pragma unroll
                for (int j = 0; j < 4; j++) acc[i][j] += a[i] * b[j];
        }
        __syncthreads();
    }
#pragma unroll
    for (int i = 0; i < 8; i++) {
        int gr = row0 + ty * 8 + i;
        if (gr < N_NODES)
            *(float4*)&g_h1[(size_t)gr * D1 + tx * 4] =
                make_float4(acc[i][0], acc[i][1], acc[i][2], acc[i][3]);
    }
}

// =============================================================================
// att1: per (node,head) attention scalars
// =============================================================================
__global__ void k_att1(const float* __restrict__ att_src, const float* __restrict__ att_dst) {
    int idx = blockIdx.x * blockDim.x + threadIdx.x;
    if (idx >= N_NODES * H1) return;
    int h = idx & 7, n = idx >> 3;
    const float4* hp = (const float4*)&g_h1[(size_t)n * D1 + h * C1];
    float4 h0 = hp[0], h1v = hp[1];
    const float4* sp = (const float4*)&att_src[h * C1];
    const float4* dp = (const float4*)&att_dst[h * C1];
    float4 s0 = sp[0], s1 = sp[1], d0 = dp[0], d1 = dp[1];
    g_as1[idx] = h0.x * s0.x + h0.y * s0.y + h0.z * s0.z + h0.w * s0.w
               + h1v.x * s1.x + h1v.y * s1.y + h1v.z * s1.z + h1v.w * s1.w;
    g_ad1[idx] = h0.x * d0.x + h0.y * d0.y + h0.z * d0.z + h0.w * d0.w
               + h1v.x * d1.x + h1v.y * d1.y + h1v.z * d1.z + h1v.w * d1.w;
}

// =============================================================================
// FUSED edge pass layer1: out1[d] += w*h1[s]; den1[d] += w.  (normalize later)
// 8 lanes per edge, lane == head.  No max-shift (self-loops, bounded logits).
// =============================================================================
__global__ void k_edge_agg1(const int* __restrict__ ei) {
    int t = blockIdx.x * blockDim.x + threadIdx.x;
    int e = t >> 3, l = t & 7;
    if (e >= EN_TOT) return;
    int s, d; edge_sd(ei, e, s, d);
    float w = __expf(lrelu(g_as1[s * H1 + l] + g_ad1[d * H1 + l]));
    const float4* hp = (const float4*)&g_h1[(size_t)s * D1 + l * C1];
    float4 h0 = hp[0], h1v = hp[1];
    float* op = &g_out1[(size_t)d * D1 + l * C1];
    red_add_v4(op,     h0.x * w, h0.y * w, h0.z * w, h0.w * w);
    red_add_v4(op + 4, h1v.x * w, h1v.y * w, h1v.z * w, h1v.w * w);
    red_add_f(&g_den1[d * H1 + l], w);
}

// =============================================================================
// layer2 prep: v = relu(out1/den1 + b1); h2 = v @ W2; att scalars.
// warp per node, W2 staged in smem.
// =============================================================================
__global__ __launch_bounds__(256) void k_l2prep(const float* __restrict__ b1,
                                                const float* __restrict__ W2,
                                                const float* __restrict__ att_src2,
                                                const float* __restrict__ att_dst2) {
    __shared__ float W2s[D1 * C2];
    __shared__ float b1s[D1];
    __shared__ float s2s[C2];
    __shared__ float d2s[C2];
    __shared__ float vbuf[8][D1];

    for (int i = threadIdx.x; i < D1 * C2; i += 256) W2s[i] = W2[i];
    if (threadIdx.x < D1) b1s[threadIdx.x] = b1[threadIdx.x];
    if (threadIdx.x < C2) s2s[threadIdx.x] = att_src2[threadIdx.x];
    if (threadIdx.x >= 64 && threadIdx.x < 64 + C2) d2s[threadIdx.x - 64] = att_dst2[threadIdx.x - 64];
    __syncthreads();

    const int w = threadIdx.x >> 5;
    const int lane = threadIdx.x & 31;
    const int n = blockIdx.x * 8 + w;
    if (n >= N_NODES) return;

    const float* in = &g_out1[(size_t)n * D1];
    const float* dn = &g_den1[(size_t)n * H1];
    float q0 = 1.f / (dn[lane >> 3] + 1e-16f);
    float q1 = 1.f / (dn[(lane + 32) >> 3] + 1e-16f);
    float v0 = in[lane]      * q0 + b1s[lane];        v0 = v0 > 0.f ? v0 : 0.f;
    float v1 = in[lane + 32] * q1 + b1s[lane + 32];   v1 = v1 > 0.f ? v1 : 0.f;
    vbuf[w][lane] = v0;
    vbuf[w][lane + 32] = v1;
    __syncwarp();

    float ps = 0.f, pd = 0.f;
    for (int c = lane; c < C2; c += 32) {
        float acc = 0.f;
#pragma unroll
        for (int k = 0; k < D1; k++) acc += vbuf[w][k] * W2s[k * C2 + c];
        g_h2[(size_t)n * C2 + c] = acc;
        ps += acc * s2s[c];
        pd += acc * d2s[c];
    }
#pragma unroll
    for (int o = 16; o; o >>= 1) {
        ps += __shfl_xor_sync(0xffffffffu, ps, o);
        pd += __shfl_xor_sync(0xffffffffu, pd, o);
    }
    if (lane == 0) { g_as2[n] = ps; g_ad2[n] = pd; }
}

// =============================================================================
// FUSED edge pass layer2: out[d] += w*h2[s]; den2[d] += w.
// 8 lanes per edge: lane l does chunk l; lanes 0,1 also chunks 8,9; lane 7 den.
// =============================================================================
__global__ void k_edge_agg2(const int* __restrict__ ei, float* __restrict__ out) {
    int t = blockIdx.x * blockDim.x + threadIdx.x;
    int e = t >> 3, l = t & 7;
    if (e >= EN_TOT) return;
    int s, d; edge_sd(ei, e, s, d);
    float w = __expf(lrelu(g_as2[s] + g_ad2[d]));
    const float4* hp = (const float4*)&g_h2[(size_t)s * C2];
    float* op = &out[(size_t)d * C2];
    float4 h = hp[l];
    red_add_v4(op + l * 4, h.x * w, h.y * w, h.z * w, h.w * w);
    if (l < 2) {
        float4 h2v = hp[8 + l];
        red_add_v4(op + (8 + l) * 4, h2v.x * w, h2v.y * w, h2v.z * w, h2v.w * w);
    }
    if (l == 7) red_add_f(&g_den2[d], w);
}

// =============================================================================
// finalize: out = log_softmax(out/den2 + b2) per node (warp/node)
// =============================================================================
__global__ __launch_bounds__(256) void k_final(float* __restrict__ out,
                                               const float* __restrict__ b2) {
    const int w = threadIdx.x >> 5;
    const int lane = threadIdx.x & 31;
    const int n = blockIdx.x * 8 + w;
    if (n >= N_NODES) return;
    float* row = &out[(size_t)n * C2];
    float q = 1.f / (g_den2[n] + 1e-16f);
    float x0 = row[lane] * q + b2[lane];
    float x1 = (lane < 8) ? row[32 + lane] * q + b2[32 + lane] : -1e30f;
    float m = fmaxf(x0, x1);
#pragma unroll
    for (int o = 16; o; o >>= 1) m = fmaxf(m, __shfl_xor_sync(0xffffffffu, m, o));
    float s = expf(x0 - m) + ((lane < 8) ? expf(x1 - m) : 0.f);
#pragma unroll
    for (int o = 16; o; o >>= 1) s += __shfl_xor_sync(0xffffffffu, s, o);
    float l = m + logf(s);
    row[lane] = x0 - l;
    if (lane < 8) row[32 + lane] = x1 - l;
}

// =============================================================================
extern "C" void kernel_launch(void* const* d_in, const int* in_sizes, int n_in,
                              void* d_out, int out_size) {
    const float* x        = (const float*)d_in[0];
    const int*   ei       = (const int*)d_in[1];
    const float* W1       = (const float*)d_in[2];
    const float* att_src1 = (const float*)d_in[3];
    const float* att_dst1 = (const float*)d_in[4];
    const float* b1       = (const float*)d_in[5];
    const float* W2       = (const float*)d_in[6];
    const float* att_src2 = (const float*)d_in[7];
    const float* att_dst2 = (const float*)d_in[8];
    const float* b2       = (const float*)d_in[9];
    float*       out      = (float*)d_out;
    (void)in_sizes; (void)n_in;

    void *p_den1, *p_out1, *p_den2;
    cudaGetSymbolAddress(&p_den1, g_den1);
    cudaGetSymbolAddress(&p_out1, g_out1);
    cudaGetSymbolAddress(&p_den2, g_den2);

    cudaMemsetAsync(p_den1, 0, (size_t)N_NODES * H1 * sizeof(float));
    cudaMemsetAsync(p_out1, 0, (size_t)N_NODES * D1 * sizeof(float));
    cudaMemsetAsync(p_den2, 0, (size_t)N_NODES * sizeof(float));
    cudaMemsetAsync(out,    0, (size_t)out_size * sizeof(float));

    const int TB = 256;
    k_gemm1<<<(N_NODES + BM - 1) / BM, TB>>>(x, W1);
    k_att1<<<(N_NODES * H1 + TB - 1) / TB, TB>>>(att_src1, att_dst1);
    k_edge_agg1<<<((EN_TOT * 8) + TB - 1) / TB, TB>>>(ei);
    k_l2prep<<<(N_NODES + 7) / 8, TB>>>(b1, W2, att_src2, att_dst2);
    k_edge_agg2<<<((EN_TOT * 8) + TB - 1) / TB, TB>>>(ei, out);
    k_final<<<(N_NODES + 7) / 8, TB>>>(out, b2);
}

// round 7
// speedup vs baseline: 1.5850x; 1.1545x over previous
#include <cuda_runtime.h>

#define N_NODES 100000
#define N_EDGES 1600000
#define EN_TOT  (N_EDGES + N_NODES)   // edges + self loops
#define F_IN    512
#define H1      8
#define C1      8
#define D1      64                    // H1*C1
#define C2      40

// ---------------- scratch (static device allocations; allowed) ----------------
__device__ float g_h1 [N_NODES * D1];   // layer1 linear output  [N,64]
__device__ float g_as1[N_NODES * H1];   // per-node src attention [N,8]
__device__ float g_ad1[N_NODES * H1];
__device__ float g_den1[N_NODES * H1];  // softmax denominators (accumulated in agg pass)
__device__ float g_out1[N_NODES * D1];  // layer1 UNNORMALIZED aggregate
__device__ float g_h2 [N_NODES * C2];   // layer2 linear output  [N,40]
__device__ float g_as2[N_NODES];
__device__ float g_ad2[N_NODES];
__device__ float g_den2[N_NODES];

__device__ __forceinline__ void red_add_v4(float* addr, float a, float b, float c, float d) {
    asm volatile("red.global.add.v4.f32 [%0], {%1,%2,%3,%4};"
                 :: "l"(addr), "f"(a), "f"(b), "f"(c), "f"(d) : "memory");
}
__device__ __forceinline__ void red_add_f(float* addr, float a) {
    asm volatile("red.global.add.f32 [%0], %1;" :: "l"(addr), "f"(a) : "memory");
}
__device__ __forceinline__ float lrelu(float e) { return e > 0.f ? e : 0.2f * e; }

// edge_index is int32 on device.
__device__ __forceinline__ void edge_sd(const int* __restrict__ ei, int i, int& s, int& d) {
    if (i < N_EDGES) { s = __ldg(&ei[i]); d = __ldg(&ei[N_EDGES + i]); }
    else             { s = d = i - N_EDGES; }
}

// =============================================================================
// GEMM1: g_h1[N,64] = x[N,512] @ W1[512,64]   (fp32 SIMT, BM=128 BN=64 BK=32)
// =============================================================================
#define BM 128
#define BN 64
#define BK 32
__global__ __launch_bounds__(256) void k_gemm1(const float* __restrict__ X,
                                               const float* __restrict__ W) {
    __shared__ float As[BK][BM + 1];
    __shared__ float Bs[BK][BN];

    const int tid = threadIdx.x;
    const int tx = tid & 15;
    const int ty = tid >> 4;
    const int row0 = blockIdx.x * BM;

    float acc[8][4] = {};

    for (int k0 = 0; k0 < F_IN; k0 += BK) {
#pragma unroll
        for (int i = 0; i < 4; i++) {
            int fid = tid + i * 256;
            int r = fid >> 3;
            int c4 = fid & 7;
            int gr = row0 + r;
            if (gr >= N_NODES) gr = N_NODES - 1;
            float4 v = *(const float4*)&X[(size_t)gr * F_IN + k0 + c4 * 4];
            As[c4 * 4 + 0][r] = v.x;
            As[c4 * 4 + 1][r] = v.y;
            As[c4 * 4 + 2][r] = v.z;
            As[c4 * 4 + 3][r] = v.w;
        }
#pragma unroll
        for (int i = 0; i < 2; i++) {
            int fid = tid + i * 256;
            int r = fid >> 4;
            int c4 = fid & 15;
            *(float4*)&Bs[r][c4 * 4] = *(const float4*)&W[(k0 + r) * BN + c4 * 4];
        }
        __syncthreads();
#pragma unroll
        for (int kk = 0; kk < BK; kk++) {
            float a[8], b[4];
#pragma unroll
            for (int i = 0; i < 8; i++) a[i] = As[kk][ty * 8 + i];
            float4 bv = *(const float4*)&Bs[kk][tx * 4];
            b[0] = bv.x; b[1] = bv.y; b[2] = bv.z; b[3] = bv.w;
#pragma unroll
            for (int i = 0; i < 8; i++)
#pragma unroll
                for (int j = 0; j < 4; j++) acc[i][j] += a[i] * b[j];
        }
        __syncthreads();
    }
#pragma unroll
    for (int i = 0; i < 8; i++) {
        int gr = row0 + ty * 8 + i;
        if (gr < N_NODES)
            *(float4*)&g_h1[(size_t)gr * D1 + tx * 4] =
                make_float4(acc[i][0], acc[i][1], acc[i][2], acc[i][3]);
    }
}

// =============================================================================
// att1: per (node,head) attention scalars
// =============================================================================
__global__ void k_att1(const float* __restrict__ att_src, const float* __restrict__ att_dst) {
    int idx = blockIdx.x * blockDim.x + threadIdx.x;
    if (idx >= N_NODES * H1) return;
    int h = idx & 7, n = idx >> 3;
    const float4* hp = (const float4*)&g_h1[(size_t)n * D1 + h * C1];
    float4 h0 = hp[0], h1v = hp[1];
    const float4* sp = (const float4*)&att_src[h * C1];
    const float4* dp = (const float4*)&att_dst[h * C1];
    float4 s0 = sp[0], s1 = sp[1], d0 = dp[0], d1 = dp[1];
    g_as1[idx] = h0.x * s0.x + h0.y * s0.y + h0.z * s0.z + h0.w * s0.w
               + h1v.x * s1.x + h1v.y * s1.y + h1v.z * s1.z + h1v.w * s1.w;
    g_ad1[idx] = h0.x * d0.x + h0.y * d0.y + h0.z * d0.z + h0.w * d0.w
               + h1v.x * d1.x + h1v.y * d1.y + h1v.z * d1.z + h1v.w * d1.w;
}

// =============================================================================
// FUSED edge pass layer1: out1[d] += w*h1[s]; den1[d] += w.  (normalize later)
// 8 lanes per edge, lane == head.  No max-shift (self-loops, bounded logits).
// =============================================================================
__global__ void k_edge_agg1(const int* __restrict__ ei) {
    int t = blockIdx.x * blockDim.x + threadIdx.x;
    int e = t >> 3, l = t & 7;
    if (e >= EN_TOT) return;
    int s, d; edge_sd(ei, e, s, d);
    float w = __expf(lrelu(g_as1[s * H1 + l] + g_ad1[d * H1 + l]));
    const float4* hp = (const float4*)&g_h1[(size_t)s * D1 + l * C1];
    float4 h0 = hp[0], h1v = hp[1];
    float* op = &g_out1[(size_t)d * D1 + l * C1];
    red_add_v4(op,     h0.x * w, h0.y * w, h0.z * w, h0.w * w);
    red_add_v4(op + 4, h1v.x * w, h1v.y * w, h1v.z * w, h1v.w * w);
    red_add_f(&g_den1[d * H1 + l], w);
}

// =============================================================================
// layer2 prep (register-blocked tiled GEMM):
//   v[row,:] = relu(out1[row,:]/den1 + b1);  h2 = v @ W2 [64x40];
//   as2/ad2 = h2 . att_{src,dst}2.
// Block: 128 rows x 40 cols, BK=64 (whole K).  256 thr = 32(ty) x 8(tx);
// thread tile 4 rows x 5 cols.  Per k-step: 1 LDS.128 + 5 LDS.32 -> 20 FFMA.
// =============================================================================
#define L2BM 128
__global__ __launch_bounds__(256) void k_l2prep(const float* __restrict__ b1,
                                                const float* __restrict__ W2,
                                                const float* __restrict__ att_src2,
                                                const float* __restrict__ att_dst2) {
    __shared__ float As[D1][L2BM + 4];   // K-major, padded: rows 132 floats (16B aligned)
    __shared__ float Bs[D1][C2];
    __shared__ float b1s[D1];
    __shared__ float s2s[C2];
    __shared__ float d2s[C2];

    const int tid = threadIdx.x;
    const int row0 = blockIdx.x * L2BM;

    for (int i = tid; i < D1 * C2; i += 256) Bs[i / C2][i % C2] = W2[i];
    if (tid < D1) b1s[tid] = b1[tid];
    if (tid >= 64 && tid < 64 + C2) s2s[tid - 64] = att_src2[tid - 64];
    if (tid >= 128 && tid < 128 + C2) d2s[tid - 128] = att_dst2[tid - 128];
    __syncthreads();

    // Load A tile: 128 rows x 16 float4 = 2048 float4, 8 per thread.
    // Apply 1/den, +b1, relu on the fly.
#pragma unroll
    for (int i = 0; i < 8; i++) {
        int fid = tid + i * 256;          // 0..2047
        int r = fid >> 4;                 // row in tile
        int c4 = fid & 15;                // float4 index in row (head = c4>>1)
        int gr = row0 + r;
        if (gr >= N_NODES) gr = N_NODES - 1;
        float q = 1.f / (g_den1[gr * H1 + (c4 >> 1)] + 1e-16f);
        float4 v = *(const float4*)&g_out1[(size_t)gr * D1 + c4 * 4];
        float e0 = v.x * q + b1s[c4 * 4 + 0];
        float e1 = v.y * q + b1s[c4 * 4 + 1];
        float e2 = v.z * q + b1s[c4 * 4 + 2];
        float e3 = v.w * q + b1s[c4 * 4 + 3];
        As[c4 * 4 + 0][r] = e0 > 0.f ? e0 : 0.f;
        As[c4 * 4 + 1][r] = e1 > 0.f ? e1 : 0.f;
        As[c4 * 4 + 2][r] = e2 > 0.f ? e2 : 0.f;
        As[c4 * 4 + 3][r] = e3 > 0.f ? e3 : 0.f;
    }
    __syncthreads();

    const int ty = tid >> 3;              // 0..31 -> 4 rows each
    const int tx = tid & 7;               // 0..7  -> 5 cols each
    float acc[4][5] = {};

#pragma unroll
    for (int k = 0; k < D1; k++) {
        float4 av = *(const float4*)&As[k][ty * 4];
        float a[4] = {av.x, av.y, av.z, av.w};
        float b[5];
#pragma unroll
        for (int j = 0; j < 5; j++) b[j] = Bs[k][tx * 5 + j];
#pragma unroll
        for (int i = 0; i < 4; i++)
#pragma unroll
            for (int j = 0; j < 5; j++) acc[i][j] += a[i] * b[j];
    }

    // Epilogue: store h2, fold att2 dot products, 8-lane reduce.
#pragma unroll
    for (int i = 0; i < 4; i++) {
        int gr = row0 + ty * 4 + i;
        float ps = 0.f, pd = 0.f;
#pragma unroll
        for (int j = 0; j < 5; j++) {
            ps += acc[i][j] * s2s[tx * 5 + j];
            pd += acc[i][j] * d2s[tx * 5 + j];
        }
#pragma unroll
        for (int o = 4; o; o >>= 1) {      // xor within 8-lane tx group (same warp)
            ps += __shfl_xor_sync(0xffffffffu, ps, o);
            pd += __shfl_xor_sync(0xffffffffu, pd, o);
        }
        if (gr < N_NODES) {
#pragma unroll
            for (int j = 0; j < 5; j++)
                g_h2[(size_t)gr * C2 + tx * 5 + j] = acc[i][j];
            if (tx == 0) { g_as2[gr] = ps; g_ad2[gr] = pd; }
        }
    }
}

// =============================================================================
// FUSED edge pass layer2: out[d] += w*h2[s]; den2[d] += w.
// 8 lanes per edge: lane l does chunk l; lanes 0,1 also chunks 8,9; lane 7 den.
// =============================================================================
__global__ void k_edge_agg2(const int* __restrict__ ei, float* __restrict__ out) {
    int t = blockIdx.x * blockDim.x + threadIdx.x;
    int e = t >> 3, l = t & 7;
    if (e >= EN_TOT) return;
    int s, d; edge_sd(ei, e, s, d);
    float w = __expf(lrelu(g_as2[s] + g_ad2[d]));
    const float4* hp = (const float4*)&g_h2[(size_t)s * C2];
    float* op = &out[(size_t)d * C2];
    float4 h = hp[l];
    red_add_v4(op + l * 4, h.x * w, h.y * w, h.z * w, h.w * w);
    if (l < 2) {
        float4 h2v = hp[8 + l];
        red_add_v4(op + (8 + l) * 4, h2v.x * w, h2v.y * w, h2v.z * w, h2v.w * w);
    }
    if (l == 7) red_add_f(&g_den2[d], w);
}

// =============================================================================
// finalize: out = log_softmax(out/den2 + b2) per node (warp/node)
// =============================================================================
__global__ __launch_bounds__(256) void k_final(float* __restrict__ out,
                                               const float* __restrict__ b2) {
    const int w = threadIdx.x >> 5;
    const int lane = threadIdx.x & 31;
    const int n = blockIdx.x * 8 + w;
    if (n >= N_NODES) return;
    float* row = &out[(size_t)n * C2];
    float q = 1.f / (g_den2[n] + 1e-16f);
    float x0 = row[lane] * q + b2[lane];
    float x1 = (lane < 8) ? row[32 + lane] * q + b2[32 + lane] : -1e30f;
    float m = fmaxf(x0, x1);
#pragma unroll
    for (int o = 16; o; o >>= 1) m = fmaxf(m, __shfl_xor_sync(0xffffffffu, m, o));
    float s = expf(x0 - m) + ((lane < 8) ? expf(x1 - m) : 0.f);
#pragma unroll
    for (int o = 16; o; o >>= 1) s += __shfl_xor_sync(0xffffffffu, s, o);
    float l = m + logf(s);
    row[lane] = x0 - l;
    if (lane < 8) row[32 + lane] = x1 - l;
}

// =============================================================================
extern "C" void kernel_launch(void* const* d_in, const int* in_sizes, int n_in,
                              void* d_out, int out_size) {
    const float* x        = (const float*)d_in[0];
    const int*   ei       = (const int*)d_in[1];
    const float* W1       = (const float*)d_in[2];
    const float* att_src1 = (const float*)d_in[3];
    const float* att_dst1 = (const float*)d_in[4];
    const float* b1       = (const float*)d_in[5];
    const float* W2       = (const float*)d_in[6];
    const float* att_src2 = (const float*)d_in[7];
    const float* att_dst2 = (const float*)d_in[8];
    const float* b2       = (const float*)d_in[9];
    float*       out      = (float*)d_out;
    (void)in_sizes; (void)n_in;

    void *p_den1, *p_out1, *p_den2;
    cudaGetSymbolAddress(&p_den1, g_den1);
    cudaGetSymbolAddress(&p_out1, g_out1);
    cudaGetSymbolAddress(&p_den2, g_den2);

    cudaMemsetAsync(p_den1, 0, (size_t)N_NODES * H1 * sizeof(float));
    cudaMemsetAsync(p_out1, 0, (size_t)N_NODES * D1 * sizeof(float));
    cudaMemsetAsync(p_den2, 0, (size_t)N_NODES * sizeof(float));
    cudaMemsetAsync(out,    0, (size_t)out_size * sizeof(float));

    const int TB = 256;
    k_gemm1<<<(N_NODES + BM - 1) / BM, TB>>>(x, W1);
    k_att1<<<(N_NODES * H1 + TB - 1) / TB, TB>>>(att_src1, att_dst1);
    k_edge_agg1<<<((EN_TOT * 8) + TB - 1) / TB, TB>>>(ei);
    k_l2prep<<<(N_NODES + L2BM - 1) / L2BM, TB>>>(b1, W2, att_src2, att_dst2);
    k_edge_agg2<<<((EN_TOT * 8) + TB - 1) / TB, TB>>>(ei, out);
    k_final<<<(N_NODES + 7) / 8, TB>>>(out, b2);
}

// round 8
// speedup vs baseline: 1.7510x; 1.1048x over previous
#include <cuda_runtime.h>
#include <cstdint>

#define N_NODES 100000
#define N_EDGES 1600000
#define EN_TOT  (N_EDGES + N_NODES)   // edges + self loops
#define F_IN    512
#define H1      8
#define C1      8
#define D1      64                    // H1*C1
#define C2      40

// ---------------- scratch (static device allocations; allowed) ----------------
__device__ float g_h1 [N_NODES * D1];   // layer1 linear output  [N,64]
__device__ float g_as1[N_NODES * H1];   // per-node src attention [N,8]
__device__ float g_ad1[N_NODES * H1];
__device__ float g_den1[N_NODES * H1];  // softmax denominators (accumulated in agg pass)
__device__ float g_out1[N_NODES * D1];  // layer1 UNNORMALIZED aggregate
__device__ float g_h2 [N_NODES * C2];   // layer2 linear output  [N,40]
__device__ float g_as2[N_NODES];
__device__ float g_ad2[N_NODES];
__device__ float g_den2[N_NODES];

__device__ __forceinline__ void red_add_v4(float* addr, float a, float b, float c, float d) {
    asm volatile("red.global.add.v4.f32 [%0], {%1,%2,%3,%4};"
                 :: "l"(addr), "f"(a), "f"(b), "f"(c), "f"(d) : "memory");
}
__device__ __forceinline__ void red_add_f(float* addr, float a) {
    asm volatile("red.global.add.f32 [%0], %1;" :: "l"(addr), "f"(a) : "memory");
}
__device__ __forceinline__ float lrelu(float e) { return e > 0.f ? e : 0.2f * e; }

__device__ __forceinline__ float to_tf32(float x) {
    uint32_t r;
    asm("cvt.rna.tf32.f32 %0, %1;" : "=r"(r) : "f"(x));
    return __uint_as_float(r);
}

// edge_index is int32 on device.
__device__ __forceinline__ void edge_sd(const int* __restrict__ ei, int i, int& s, int& d) {
    if (i < N_EDGES) { s = __ldg(&ei[i]); d = __ldg(&ei[N_EDGES + i]); }
    else             { s = d = i - N_EDGES; }
}

// =============================================================================
// GEMM1 (tf32 tensor-core): g_h1[N,64] = x[N,512] @ W1[512,64]
// BM=128 BN=64 BK=32, 256 thr = 8 warps (4 along M x 2 along N), warp = 32x32.
// mma.sync.m16n8k8.row.col tf32; smem K-major with pad=8 -> bank index
// 8*(k%4)+(m%8) is a 0..31 permutation => conflict-free fragment loads.
// =============================================================================
#define BM 128
#define BN 64
#define BK 32
__global__ __launch_bounds__(256) void k_gemm1(const float* __restrict__ X,
                                               const float* __restrict__ W) {
    __shared__ float As[BK][BM + 8];   // [k][m], row stride 136 floats
    __shared__ float Bs[BK][BN + 8];   // [k][n], row stride 72 floats

    const int tid  = threadIdx.x;
    const int wid  = tid >> 5;
    const int lane = tid & 31;
    const int wm   = wid & 3;          // 0..3 : 32-row slab
    const int wn   = wid >> 2;         // 0..1 : 32-col slab
    const int lr   = lane >> 2;        // 0..7
    const int lc   = lane & 3;         // 0..3
    const int row0 = blockIdx.x * BM;

    float acc[2][4][4] = {};

    for (int k0 = 0; k0 < F_IN; k0 += BK) {
        // A tile: 128x32 floats = 1024 float4, 4 per thread, cvt->tf32, K-major scatter
#pragma unroll
        for (int i = 0; i < 4; i++) {
            int fid = tid + i * 256;
            int r = fid >> 3;               // 0..127
            int c4 = fid & 7;               // 0..7
            int gr = row0 + r;
            if (gr >= N_NODES) gr = N_NODES - 1;
            float4 v = *(const float4*)&X[(size_t)gr * F_IN + k0 + c4 * 4];
            As[c4 * 4 + 0][r] = to_tf32(v.x);
            As[c4 * 4 + 1][r] = to_tf32(v.y);
            As[c4 * 4 + 2][r] = to_tf32(v.z);
            As[c4 * 4 + 3][r] = to_tf32(v.w);
        }
        // B tile: 32x64 floats = 512 float4, 2 per thread
#pragma unroll
        for (int i = 0; i < 2; i++) {
            int fid = tid + i * 256;
            int r = fid >> 4;               // 0..31
            int c4 = fid & 15;              // 0..15
            float4 v = *(const float4*)&W[(k0 + r) * BN + c4 * 4];
            float4 t = make_float4(to_tf32(v.x), to_tf32(v.y), to_tf32(v.z), to_tf32(v.w));
            *(float4*)&Bs[r][c4 * 4] = t;
        }
        __syncthreads();

#pragma unroll
        for (int kk = 0; kk < BK; kk += 8) {
            uint32_t a[2][4], b[4][2];
#pragma unroll
            for (int mt = 0; mt < 2; mt++) {
                int m0 = wm * 32 + mt * 16;
                a[mt][0] = __float_as_uint(As[kk + lc    ][m0 + lr    ]);
                a[mt][1] = __float_as_uint(As[kk + lc    ][m0 + lr + 8]);
                a[mt][2] = __float_as_uint(As[kk + lc + 4][m0 + lr    ]);
                a[mt][3] = __float_as_uint(As[kk + lc + 4][m0 + lr + 8]);
            }
#pragma unroll
            for (int nt = 0; nt < 4; nt++) {
                int n0 = wn * 32 + nt * 8;
                b[nt][0] = __float_as_uint(Bs[kk + lc    ][n0 + lr]);
                b[nt][1] = __float_as_uint(Bs[kk + lc + 4][n0 + lr]);
            }
#pragma unroll
            for (int mt = 0; mt < 2; mt++)
#pragma unroll
                for (int nt = 0; nt < 4; nt++) {
                    asm volatile(
                        "mma.sync.aligned.m16n8k8.row.col.f32.tf32.tf32.f32 "
                        "{%0,%1,%2,%3}, {%4,%5,%6,%7}, {%8,%9}, {%0,%1,%2,%3};"
                        : "+f"(acc[mt][nt][0]), "+f"(acc[mt][nt][1]),
                          "+f"(acc[mt][nt][2]), "+f"(acc[mt][nt][3])
                        : "r"(a[mt][0]), "r"(a[mt][1]), "r"(a[mt][2]), "r"(a[mt][3]),
                          "r"(b[nt][0]), "r"(b[nt][1]));
                }
        }
        __syncthreads();
    }

    // Epilogue: c0/c1 cols adjacent -> float2 stores
#pragma unroll
    for (int mt = 0; mt < 2; mt++) {
#pragma unroll
        for (int nt = 0; nt < 4; nt++) {
            int r0 = row0 + wm * 32 + mt * 16 + lr;
            int c0 = wn * 32 + nt * 8 + 2 * lc;
            if (r0 < N_NODES)
                *(float2*)&g_h1[(size_t)r0 * D1 + c0] =
                    make_float2(acc[mt][nt][0], acc[mt][nt][1]);
            if (r0 + 8 < N_NODES)
                *(float2*)&g_h1[(size_t)(r0 + 8) * D1 + c0] =
                    make_float2(acc[mt][nt][2], acc[mt][nt][3]);
        }
    }
}

// =============================================================================
// att1: per (node,head) attention scalars
// =============================================================================
__global__ void k_att1(const float* __restrict__ att_src, const float* __restrict__ att_dst) {
    int idx = blockIdx.x * blockDim.x + threadIdx.x;
    if (idx >= N_NODES * H1) return;
    int h = idx & 7, n = idx >> 3;
    const float4* hp = (const float4*)&g_h1[(size_t)n * D1 + h * C1];
    float4 h0 = hp[0], h1v = hp[1];
    const float4* sp = (const float4*)&att_src[h * C1];
    const float4* dp = (const float4*)&att_dst[h * C1];
    float4 s0 = sp[0], s1 = sp[1], d0 = dp[0], d1 = dp[1];
    g_as1[idx] = h0.x * s0.x + h0.y * s0.y + h0.z * s0.z + h0.w * s0.w
               + h1v.x * s1.x + h1v.y * s1.y + h1v.z * s1.z + h1v.w * s1.w;
    g_ad1[idx] = h0.x * d0.x + h0.y * d0.y + h0.z * d0.z + h0.w * d0.w
               + h1v.x * d1.x + h1v.y * d1.y + h1v.z * d1.z + h1v.w * d1.w;
}

// =============================================================================
// FUSED edge pass layer1: out1[d] += w*h1[s]; den1[d] += w.  (normalize later)
// 8 lanes per edge, lane == head.  No max-shift (self-loops, bounded logits).
// =============================================================================
__global__ void k_edge_agg1(const int* __restrict__ ei) {
    int t = blockIdx.x * blockDim.x + threadIdx.x;
    int e = t >> 3, l = t & 7;
    if (e >= EN_TOT) return;
    int s, d; edge_sd(ei, e, s, d);
    float w = __expf(lrelu(g_as1[s * H1 + l] + g_ad1[d * H1 + l]));
    const float4* hp = (const float4*)&g_h1[(size_t)s * D1 + l * C1];
    float4 h0 = hp[0], h1v = hp[1];
    float* op = &g_out1[(size_t)d * D1 + l * C1];
    red_add_v4(op,     h0.x * w, h0.y * w, h0.z * w, h0.w * w);
    red_add_v4(op + 4, h1v.x * w, h1v.y * w, h1v.z * w, h1v.w * w);
    red_add_f(&g_den1[d * H1 + l], w);
}

// =============================================================================
// layer2 prep (register-blocked tiled GEMM):
//   v = relu(out1/den1 + b1);  h2 = v @ W2;  as2/ad2 = h2 . att2.
// =============================================================================
#define L2BM 128
__global__ __launch_bounds__(256) void k_l2prep(const float* __restrict__ b1,
                                                const float* __restrict__ W2,
                                                const float* __restrict__ att_src2,
                                                const float* __restrict__ att_dst2) {
    __shared__ float As[D1][L2BM + 4];
    __shared__ float Bs[D1][C2];
    __shared__ float b1s[D1];
    __shared__ float s2s[C2];
    __shared__ float d2s[C2];

    const int tid = threadIdx.x;
    const int row0 = blockIdx.x * L2BM;

    for (int i = tid; i < D1 * C2; i += 256) Bs[i / C2][i % C2] = W2[i];
    if (tid < D1) b1s[tid] = b1[tid];
    if (tid >= 64 && tid < 64 + C2) s2s[tid - 64] = att_src2[tid - 64];
    if (tid >= 128 && tid < 128 + C2) d2s[tid - 128] = att_dst2[tid - 128];
    __syncthreads();

#pragma unroll
    for (int i = 0; i < 8; i++) {
        int fid = tid + i * 256;
        int r = fid >> 4;
        int c4 = fid & 15;
        int gr = row0 + r;
        if (gr >= N_NODES) gr = N_NODES - 1;
        float q = 1.f / (g_den1[gr * H1 + (c4 >> 1)] + 1e-16f);
        float4 v = *(const float4*)&g_out1[(size_t)gr * D1 + c4 * 4];
        float e0 = v.x * q + b1s[c4 * 4 + 0];
        float e1 = v.y * q + b1s[c4 * 4 + 1];
        float e2 = v.z * q + b1s[c4 * 4 + 2];
        float e3 = v.w * q + b1s[c4 * 4 + 3];
        As[c4 * 4 + 0][r] = e0 > 0.f ? e0 : 0.f;
        As[c4 * 4 + 1][r] = e1 > 0.f ? e1 : 0.f;
        As[c4 * 4 + 2][r] = e2 > 0.f ? e2 : 0.f;
        As[c4 * 4 + 3][r] = e3 > 0.f ? e3 : 0.f;
    }
    __syncthreads();

    const int ty = tid >> 3;
    const int tx = tid & 7;
    float acc[4][5] = {};

#pragma unroll
    for (int k = 0; k < D1; k++) {
        float4 av = *(const float4*)&As[k][ty * 4];
        float a[4] = {av.x, av.y, av.z, av.w};
        float b[5];
#pragma unroll
        for (int j = 0; j < 5; j++) b[j] = Bs[k][tx * 5 + j];
#pragma unroll
        for (int i = 0; i < 4; i++)
#pragma unroll
            for (int j = 0; j < 5; j++) acc[i][j] += a[i] * b[j];
    }

#pragma unroll
    for (int i = 0; i < 4; i++) {
        int gr = row0 + ty * 4 + i;
        float ps = 0.f, pd = 0.f;
#pragma unroll
        for (int j = 0; j < 5; j++) {
            ps += acc[i][j] * s2s[tx * 5 + j];
            pd += acc[i][j] * d2s[tx * 5 + j];
        }
#pragma unroll
        for (int o = 4; o; o >>= 1) {
            ps += __shfl_xor_sync(0xffffffffu, ps, o);
            pd += __shfl_xor_sync(0xffffffffu, pd, o);
        }
        if (gr < N_NODES) {
#pragma unroll
            for (int j = 0; j < 5; j++)
                g_h2[(size_t)gr * C2 + tx * 5 + j] = acc[i][j];
            if (tx == 0) { g_as2[gr] = ps; g_ad2[gr] = pd; }
        }
    }
}

// =============================================================================
// FUSED edge pass layer2: out[d] += w*h2[s]; den2[d] += w.
// =============================================================================
__global__ void k_edge_agg2(const int* __restrict__ ei, float* __restrict__ out) {
    int t = blockIdx.x * blockDim.x + threadIdx.x;
    int e = t >> 3, l = t & 7;
    if (e >= EN_TOT) return;
    int s, d; edge_sd(ei, e, s, d);
    float w = __expf(lrelu(g_as2[s] + g_ad2[d]));
    const float4* hp = (const float4*)&g_h2[(size_t)s * C2];
    float* op = &out[(size_t)d * C2];
    float4 h = hp[l];
    red_add_v4(op + l * 4, h.x * w, h.y * w, h.z * w, h.w * w);
    if (l < 2) {
        float4 h2v = hp[8 + l];
        red_add_v4(op + (8 + l) * 4, h2v.x * w, h2v.y * w, h2v.z * w, h2v.w * w);
    }
    if (l == 7) red_add_f(&g_den2[d], w);
}

// =============================================================================
// finalize: out = log_softmax(out/den2 + b2) per node (warp/node)
// =============================================================================
__global__ __launch_bounds__(256) void k_final(float* __restrict__ out,
                                               const float* __restrict__ b2) {
    const int w = threadIdx.x >> 5;
    const int lane = threadIdx.x & 31;
    const int n = blockIdx.x * 8 + w;
    if (n >= N_NODES) return;
    float* row = &out[(size_t)n * C2];
    float q = 1.f / (g_den2[n] + 1e-16f);
    float x0 = row[lane] * q + b2[lane];
    float x1 = (lane < 8) ? row[32 + lane] * q + b2[32 + lane] : -1e30f;
    float m = fmaxf(x0, x1);
#pragma unroll
    for (int o = 16; o; o >>= 1) m = fmaxf(m, __shfl_xor_sync(0xffffffffu, m, o));
    float s = expf(x0 - m) + ((lane < 8) ? expf(x1 - m) : 0.f);
#pragma unroll
    for (int o = 16; o; o >>= 1) s += __shfl_xor_sync(0xffffffffu, s, o);
    float l = m + logf(s);
    row[lane] = x0 - l;
    if (lane < 8) row[32 + lane] = x1 - l;
}

// =============================================================================
extern "C" void kernel_launch(void* const* d_in, const int* in_sizes, int n_in,
                              void* d_out, int out_size) {
    const float* x        = (const float*)d_in[0];
    const int*   ei       = (const int*)d_in[1];
    const float* W1       = (const float*)d_in[2];
    const float* att_src1 = (const float*)d_in[3];
    const float* att_dst1 = (const float*)d_in[4];
    const float* b1       = (const float*)d_in[5];
    const float* W2       = (const float*)d_in[6];
    const float* att_src2 = (const float*)d_in[7];
    const float* att_dst2 = (const float*)d_in[8];
    const float* b2       = (const float*)d_in[9];
    float*       out      = (float*)d_out;
    (void)in_sizes; (void)n_in;

    void *p_den1, *p_out1, *p_den2;
    cudaGetSymbolAddress(&p_den1, g_den1);
    cudaGetSymbolAddress(&p_out1, g_out1);
    cudaGetSymbolAddress(&p_den2, g_den2);

    cudaMemsetAsync(p_den1, 0, (size_t)N_NODES * H1 * sizeof(float));
    cudaMemsetAsync(p_out1, 0, (size_t)N_NODES * D1 * sizeof(float));
    cudaMemsetAsync(p_den2, 0, (size_t)N_NODES * sizeof(float));
    cudaMemsetAsync(out,    0, (size_t)out_size * sizeof(float));

    const int TB = 256;
    k_gemm1<<<(N_NODES + BM - 1) / BM, TB>>>(x, W1);
    k_att1<<<(N_NODES * H1 + TB - 1) / TB, TB>>>(att_src1, att_dst1);
    k_edge_agg1<<<((EN_TOT * 8) + TB - 1) / TB, TB>>>(ei);
    k_l2prep<<<(N_NODES + L2BM - 1) / L2BM, TB>>>(b1, W2, att_src2, att_dst2);
    k_edge_agg2<<<((EN_TOT * 8) + TB - 1) / TB, TB>>>(ei, out);
    k_final<<<(N_NODES + 7) / 8, TB>>>(out, b2);
}